// round 16
// baseline (speedup 1.0000x reference)
#include <cuda_runtime.h>
#include <cuda_bf16.h>
#include <mma.h>
#include <cstdint>
#include <math.h>

using namespace nvcuda;

#define NB   32
#define NQ   900
#define NMM  300
#define MPAD 384            // matched rows padded for 128-tiles
#define ND   256
#define NCLS 90
#define NNC  91
#define KB   5
#define NCAND 5             // candidates per (row, nTile)
#define NT   15             // n tiles of 64 (15*64=960 >= 900)
#define NCTOT (NT*NCAND)    // 75 candidates per row
#define NRER 10             // exact-reranked candidates per row
#define NROW (NCLS*KB)      // 450 boundary rows per batch
#define NEGINF -1000000000.0f
#define SLD  72             // smem leading dim (bf16 elements), 144B rows
#define TILEA 18432u        // 128*72*2 bytes (A chunk)
#define TILEBB 9216u        // 64*72*2 bytes (B chunk)
#define BUFB  (TILEA + TILEBB)   // 27648 per buffer
#define SMEMT (2u*BUFB)          // 55296 total

// -------- scratch (device globals; no allocation allowed) --------
__device__ __align__(128) float g_matched[NB*NMM*ND];     // gathered matched embeddings (raw)
__device__ __align__(128) float g_minv[NB*NMM];           // 1/||matched||
__device__ __align__(128) float g_qinv[NB*NQ];            // 1/||obj||
__device__ __align__(128) int   g_ism[NB*NQ];             // is-matched mask per (b,q)
__device__ __align__(128) float g_sims[NB*NMM*NCLS];      // matched_n . protos (fp32 exact)
__device__ __align__(128) float g_pinv[NCLS];             // 1/||proto||
__device__ __align__(128) int   g_topi[NB*NROW];          // top-K_B indices per (b,c,k), -1 invalid
__device__ __align__(128) __nv_bfloat16 g_Mh[NB*MPAD*ND]; // matched_n hi (padded rows zero)
__device__ __align__(128) __nv_bfloat16 g_Ml[NB*MPAD*ND]; // matched_n lo
__device__ __align__(128) __nv_bfloat16 g_Bh[NB*NQ*ND];   // obj_n hi
__device__ __align__(128) float g_pv[NB*NMM*NCTOT];       // approx top5 values per (row,nTile)
__device__ __align__(128) int   g_pq[NB*NMM*NCTOT];       // approx top5 q per (row,nTile)
__device__ __align__(128) float g_fv[NB*NMM*KB];          // exact top5 values per matched row
__device__ __align__(128) int   g_fq[NB*NMM*KB];          // exact top5 q per matched row
__device__ __align__(128) float g_lseP[NCLS];
__device__ __align__(128) float g_lseneg[NCLS];
__device__ double g_acc[3];   // 0: sum fl, 1: count sg_valid, 2: sum cec terms

// -------- helpers --------
__device__ __forceinline__ float logaddexpf_(float a, float b) {
    float m = fmaxf(a, b);
    return m + log1pf(expf(-fabsf(a - b)));
}

// insert (v,id) into sorted-desc top-K, tie -> lower id first (jax top_k semantics)
template<int K>
__device__ __forceinline__ void insK(float v, int id, float* vals, int* ids) {
    #pragma unroll
    for (int j = 0; j < K; j++) {
        bool better = (v > vals[j]) || (v == vals[j] && id < ids[j]);
        if (better) {
            float tv = vals[j]; int ti = ids[j];
            vals[j] = v; ids[j] = id;
            v = tv; id = ti;
        }
    }
}

__device__ __forceinline__ void split_bf16(float a, unsigned short& h, unsigned short& l) {
    __nv_bfloat16 hb = __float2bfloat16(a);
    float hf = __bfloat162float(hb);
    __nv_bfloat16 lb = __float2bfloat16(a - hf);
    h = __bfloat16_as_ushort(hb);
    l = __bfloat16_as_ushort(lb);
}

__device__ __forceinline__ void cp16(uint32_t s, const void* g) {
    asm volatile("cp.async.ca.shared.global [%0], [%1], 16;" :: "r"(s), "l"(g));
}
__device__ __forceinline__ void cp16z(uint32_t s, const void* g, int sz) {
    asm volatile("cp.async.ca.shared.global [%0], [%1], 16, %2;" :: "r"(s), "l"(g), "r"(sz));
}

// ordered-uint encoding of float: preserves > ordering
__device__ __forceinline__ unsigned int ford(float f) {
    unsigned int u = __float_as_uint(f);
    return (u & 0x80000000u) ? ~u : (u | 0x80000000u);
}

// -------- kernels --------

// one warp per obj row: normalize + bf16 hi split + qinv + clear is_m (+ zero g_acc)
__global__ void pack_obj_kernel(const float* __restrict__ obj) {
    if (blockIdx.x == 0 && threadIdx.x < 3) g_acc[threadIdx.x] = 0.0;
    int warp = (blockIdx.x * blockDim.x + threadIdx.x) >> 5;
    int lane = threadIdx.x & 31;
    if (warp >= NB*NQ) return;
    const float4* r4 = (const float4*)(obj + (size_t)warp * ND);
    float4 a = r4[lane];
    float4 c = r4[lane + 32];
    float ss = a.x*a.x + a.y*a.y + a.z*a.z + a.w*a.w
             + c.x*c.x + c.y*c.y + c.z*c.z + c.w*c.w;
    #pragma unroll
    for (int o = 16; o; o >>= 1) ss += __shfl_xor_sync(0xffffffffu, ss, o);
    float inv = 1.0f / fmaxf(sqrtf(ss), 1e-12f);
    unsigned short h0,h1,h2,h3,l0,l1,l2,l3;
    uint2 hv;
    split_bf16(a.x*inv,h0,l0); split_bf16(a.y*inv,h1,l1);
    split_bf16(a.z*inv,h2,l2); split_bf16(a.w*inv,h3,l3);
    hv.x = h0 | ((unsigned)h1<<16); hv.y = h2 | ((unsigned)h3<<16);
    ((uint2*)g_Bh)[(size_t)warp*64 + lane] = hv;
    split_bf16(c.x*inv,h0,l0); split_bf16(c.y*inv,h1,l1);
    split_bf16(c.z*inv,h2,l2); split_bf16(c.w*inv,h3,l3);
    hv.x = h0 | ((unsigned)h1<<16); hv.y = h2 | ((unsigned)h3<<16);
    ((uint2*)g_Bh)[(size_t)warp*64 + lane + 32] = hv;
    if (lane == 0) { g_ism[warp] = 0; g_qinv[warp] = inv; }
}

// one warp per padded matched row: gather + norm + is_m + fp32 copy + bf16 hi/lo
__global__ void gather_pack_kernel(const float* __restrict__ obj, const int* __restrict__ src) {
    int warp = (blockIdx.x * blockDim.x + threadIdx.x) >> 5;
    int lane = threadIdx.x & 31;
    if (warp >= NB*MPAD) return;
    int b = warp / MPAD, n = warp - b*MPAD;
    size_t mrow = (size_t)b*MPAD + n;
    if (n >= NMM) {
        uint2 z = make_uint2(0,0);
        ((uint2*)g_Mh)[mrow*64 + lane] = z;
        ((uint2*)g_Mh)[mrow*64 + lane + 32] = z;
        ((uint2*)g_Ml)[mrow*64 + lane] = z;
        ((uint2*)g_Ml)[mrow*64 + lane + 32] = z;
        return;
    }
    int idx = src[b*NMM + n];
    const float4* r4 = (const float4*)(obj + ((size_t)b*NQ + idx) * ND);
    float4 a = r4[lane];
    float4 c = r4[lane + 32];
    float4* o4 = (float4*)(g_matched + ((size_t)b*NMM + n) * ND);
    o4[lane] = a; o4[lane + 32] = c;
    float ss = a.x*a.x + a.y*a.y + a.z*a.z + a.w*a.w
             + c.x*c.x + c.y*c.y + c.z*c.z + c.w*c.w;
    #pragma unroll
    for (int o = 16; o; o >>= 1) ss += __shfl_xor_sync(0xffffffffu, ss, o);
    float inv = 1.0f / fmaxf(sqrtf(ss), 1e-12f);
    unsigned short h0,h1,h2,h3,l0,l1,l2,l3;
    uint2 hv, lv;
    split_bf16(a.x*inv,h0,l0); split_bf16(a.y*inv,h1,l1);
    split_bf16(a.z*inv,h2,l2); split_bf16(a.w*inv,h3,l3);
    hv.x = h0 | ((unsigned)h1<<16); hv.y = h2 | ((unsigned)h3<<16);
    lv.x = l0 | ((unsigned)l1<<16); lv.y = l2 | ((unsigned)l3<<16);
    ((uint2*)g_Mh)[mrow*64 + lane] = hv;
    ((uint2*)g_Ml)[mrow*64 + lane] = lv;
    split_bf16(c.x*inv,h0,l0); split_bf16(c.y*inv,h1,l1);
    split_bf16(c.z*inv,h2,l2); split_bf16(c.w*inv,h3,l3);
    hv.x = h0 | ((unsigned)h1<<16); hv.y = h2 | ((unsigned)h3<<16);
    lv.x = l0 | ((unsigned)l1<<16); lv.y = l2 | ((unsigned)l3<<16);
    ((uint2*)g_Mh)[mrow*64 + lane + 32] = hv;
    ((uint2*)g_Ml)[mrow*64 + lane + 32] = lv;
    if (lane == 0) {
        g_minv[b*NMM + n] = inv;
        g_ism[b*NQ + idx] = 1;
    }
}

// (s2): sims[r, c] = minv[r] * (matched[r] . protos[c]) ; fp32 exact
__global__ __launch_bounds__(256) void sims_kernel(const float* __restrict__ protos) {
    __shared__ __align__(16) float As[16*ND];
    __shared__ float sminv[16];
    int r0 = blockIdx.x * 16;
    int tid = threadIdx.x;
    float4* s4 = (float4*)As;
    const float4* gm4 = (const float4*)(g_matched + (size_t)r0 * ND);
    for (int i = tid; i < 16*ND/4; i += 256) s4[i] = gm4[i];
    if (tid < 16) sminv[tid] = g_minv[r0 + tid];
    __syncthreads();
    for (int o = tid; o < 16*NCLS; o += 256) {
        int r = o / NCLS;
        int c = o - r*NCLS;
        const float4* p4 = (const float4*)(protos + (size_t)c * ND);
        const float4* a4 = (const float4*)(As + r * ND);
        float acc = 0.f;
        #pragma unroll 8
        for (int t = 0; t < ND/4; t++) {
            float4 a = a4[t];
            float4 p = __ldg(p4 + t);
            acc += a.x*p.x + a.y*p.y + a.z*p.z + a.w*p.w;
        }
        g_sims[(size_t)(r0 + r)*NCLS + c] = acc * sminv[r];
    }
}

// (s0): S = matched_n @ obj_n^T via WMMA bf16 2-term hi/lo.
// Block tile 128x64: 4 acc fragments/warp (32 regs) -> 4 CTAs/SM (R15: occ 44%, 109us).
__global__ __launch_bounds__(256, 4) void simbu_wmma_kernel() {
    extern __shared__ __align__(16) char dsm[];   // [A0(18KB), B0(9KB), A1, B1]
    __shared__ int smask[64];
    int tid = threadIdx.x, wid = tid >> 5, lane = tid & 31;
    int nT = blockIdx.x, mT = blockIdx.y, b = blockIdx.z;
    const int mBase = mT*128, nBase = nT*64;
    uint32_t sbase = (uint32_t)__cvta_generic_to_shared(dsm);

    if (tid < 64) {
        int n = nBase + tid;
        smask[tid] = (n < NQ) ? g_ism[b*NQ + n] : 2;
    }

    wmma::fragment<wmma::accumulator, 16, 16, 16, float> acc[4];
    #pragma unroll
    for (int i = 0; i < 4; i++) wmma::fill_fragment(acc[i], 0.0f);

    // chunk = seg*4 + kc; segments: 0:(Mh,Bh) 1:(Ml,Bh); K-chunk = 64 bf16
    #define ISSUE_CHUNK(chunk) do {                                                   \
        int seg_ = (chunk) >> 2, kc_ = (chunk) & 3, bi_ = (chunk) & 1;                \
        const __nv_bfloat16* Asrc_ = seg_ ? g_Ml : g_Mh;                              \
        uint32_t sa_ = sbase + (uint32_t)bi_ * BUFB;                                  \
        uint32_t sb_ = sa_ + TILEA;                                                   \
        _Pragma("unroll")                                                             \
        for (int i_ = 0; i_ < 4; i_++) {                                              \
            int e_ = i_*256 + tid;                                                    \
            int r_ = e_ >> 3, g_ = e_ & 7;                                            \
            cp16(sa_ + (uint32_t)(r_*144 + g_*16),                                    \
                 Asrc_ + ((size_t)(b*MPAD + mBase + r_)*ND + kc_*64 + g_*8));         \
        }                                                                             \
        _Pragma("unroll")                                                             \
        for (int i_ = 0; i_ < 2; i_++) {                                              \
            int e_ = i_*256 + tid;                                                    \
            int r_ = e_ >> 3, g_ = e_ & 7;                                            \
            int br_ = nBase + r_;                                                     \
            cp16z(sb_ + (uint32_t)(r_*144 + g_*16),                                   \
                  g_Bh + ((size_t)b*NQ + (br_ < NQ ? br_ : 0))*ND + kc_*64 + g_*8,    \
                  (br_ < NQ) ? 16 : 0);                                               \
        }                                                                             \
        asm volatile("cp.async.commit_group;" ::: "memory");                          \
    } while (0)

    ISSUE_CHUNK(0);
    for (int c = 0; c < 8; c++) {
        if (c + 1 < 8) {
            ISSUE_CHUNK(c + 1);
            asm volatile("cp.async.wait_group 1;" ::: "memory");
        } else {
            asm volatile("cp.async.wait_group 0;" ::: "memory");
        }
        __syncthreads();
        int bi = c & 1;
        const __nv_bfloat16* Ab = (const __nv_bfloat16*)(dsm + (size_t)bi*BUFB);
        const __nv_bfloat16* Bb = (const __nv_bfloat16*)(dsm + (size_t)bi*BUFB + TILEA);
        #pragma unroll
        for (int ks = 0; ks < 4; ks++) {
            wmma::fragment<wmma::matrix_a, 16, 16, 16, __nv_bfloat16, wmma::row_major> af;
            wmma::load_matrix_sync(af, Ab + (wid*16)*SLD + ks*16, SLD);
            #pragma unroll
            for (int nt = 0; nt < 4; nt++) {
                wmma::fragment<wmma::matrix_b, 16, 16, 16, __nv_bfloat16, wmma::col_major> bf;
                wmma::load_matrix_sync(bf, Bb + (nt*16)*SLD + ks*16, SLD);
                wmma::mma_sync(acc[nt], af, bf, acc[nt]);
            }
        }
        __syncthreads();
    }
    #undef ISSUE_CHUNK

    // epilogue: per-warp 16x20 f32 staging buffer aliased over buffer 0
    float* ebuf = reinterpret_cast<float*>(dsm) + (size_t)wid * 320;
    float tv[NCAND]; int tq[NCAND];
    #pragma unroll
    for (int j = 0; j < NCAND; j++) { tv[j] = -1e30f; tq[j] = 0x7fffffff; }
    #pragma unroll
    for (int nt = 0; nt < 4; nt++) {
        wmma::store_matrix_sync(ebuf, acc[nt], 20, wmma::mem_row_major);
        __syncwarp();
        if (lane < 16) {
            #pragma unroll
            for (int cc = 0; cc < 16; cc++) {
                int col = nt*16 + cc;
                int mk = smask[col];
                float v; int id;
                if (mk == 2)      { v = -1e30f; id = 0x7fffffff; }
                else if (mk == 1) { v = NEGINF; id = nBase + col; }
                else              { v = ebuf[lane*20 + cc]; id = nBase + col; }
                if (!(v < tv[NCAND-1])) insK<NCAND>(v, id, tv, tq);
            }
        }
        __syncwarp();
    }
    if (lane < 16) {
        int m = mBase + wid*16 + lane;
        if (m < NMM) {
            size_t base = ((size_t)(b*NMM + m)*NT + nT)*NCAND;
            #pragma unroll
            for (int j = 0; j < NCAND; j++) { g_pv[base+j] = tv[j]; g_pq[base+j] = tq[j]; }
        }
    }
}

// (s0): warp-parallel approx preselect (top-10 of 75 via iterated warp-argmax on
// packed keys), then exact fp32 rerank of the 10.
__global__ __launch_bounds__(256) void rerank_kernel(const float* __restrict__ obj) {
    int warp = (blockIdx.x * blockDim.x + threadIdx.x) >> 5;
    int lane = threadIdx.x & 31;
    if (warp >= NB*NMM) return;
    int b = warp / NMM;
    float minv = g_minv[warp];
    const float4* mr = (const float4*)(g_matched + (size_t)warp * ND);
    float4 m0 = mr[lane*2], m1 = mr[lane*2 + 1];

    // lane owns candidates lane, lane+32, lane+64 (valid < 75); pack sortable keys.
    size_t pbase = (size_t)warp * NCTOT;
    unsigned long long k0 = 0ull, k1 = 0ull, k2 = 0ull;
    {
        float v = g_pv[pbase + lane];
        int   q = g_pq[pbase + lane];
        if (v > -1e8f && q != 0x7fffffff)
            k0 = ((unsigned long long)ford(v) << 32) | (unsigned)(0x7fffffff - q);
        float v1 = g_pv[pbase + lane + 32];
        int   q1 = g_pq[pbase + lane + 32];
        if (v1 > -1e8f && q1 != 0x7fffffff)
            k1 = ((unsigned long long)ford(v1) << 32) | (unsigned)(0x7fffffff - q1);
        if (lane + 64 < NCTOT) {
            float v2 = g_pv[pbase + lane + 64];
            int   q2 = g_pq[pbase + lane + 64];
            if (v2 > -1e8f && q2 != 0x7fffffff)
                k2 = ((unsigned long long)ford(v2) << 32) | (unsigned)(0x7fffffff - q2);
        }
    }

    // iterated warp-argmax: select top-NRER keys
    int selq[NRER];
    #pragma unroll
    for (int t = 0; t < NRER; t++) {
        unsigned long long m = (k0 > k1) ? k0 : k1;
        if (k2 > m) m = k2;
        #pragma unroll
        for (int o = 16; o; o >>= 1) {
            unsigned long long m2 = __shfl_xor_sync(0xffffffffu, m, o);
            if (m2 > m) m = m2;
        }
        selq[t] = (m != 0ull) ? (0x7fffffff - (int)(m & 0xffffffffu)) : -1;
        if (k0 == m) k0 = 0ull;
        if (k1 == m) k1 = 0ull;
        if (k2 == m) k2 = 0ull;
    }

    // exact rerank: buffered partial dots for MLP, then reduce
    float pd[NRER];
    #pragma unroll
    for (int t = 0; t < NRER; t++) {
        float d = 0.f;
        int q = selq[t];
        if (q >= 0) {
            const float4* ur = (const float4*)(obj + ((size_t)b*NQ + q) * ND);
            float4 u0 = ur[lane*2], u1 = ur[lane*2 + 1];
            d = m0.x*u0.x + m0.y*u0.y + m0.z*u0.z + m0.w*u0.w
              + m1.x*u1.x + m1.y*u1.y + m1.z*u1.z + m1.w*u1.w;
        }
        pd[t] = d;
    }
    float fv[5]; int fq[5];
    #pragma unroll
    for (int j = 0; j < 5; j++) { fv[j] = -1e30f; fq[j] = 0x7fffffff; }
    #pragma unroll
    for (int t = 0; t < NRER; t++) {
        float d = pd[t];
        #pragma unroll
        for (int o = 16; o; o >>= 1) d += __shfl_xor_sync(0xffffffffu, d, o);
        int q = selq[t];
        if (q >= 0) {
            float sim = d * minv * g_qinv[b*NQ + q];
            insK<5>(sim, q, fv, fq);
        }
    }
    if (lane == 0) {
        #pragma unroll
        for (int j = 0; j < 5; j++) {
            g_fv[(size_t)warp*5 + j] = fv[j];
            g_fq[(size_t)warp*5 + j] = fq[j];
        }
    }
}

// (s2): per (b,c): top-5 of dist = 1 - sim over n with label==c
__global__ void topk_dists_kernel(const int* __restrict__ labels) {
    int bc = blockIdx.x;
    int b = bc / NCLS, c = bc - b*NCLS;
    int lane = threadIdx.x;
    float lv[5]; int li[5];
    #pragma unroll
    for (int j = 0; j < 5; j++) { lv[j] = -1e30f; li[j] = 0x7fffffff; }
    int cnt = 0;
    for (int n = lane; n < NMM; n += 32) {
        if (labels[b*NMM + n] == c) {
            cnt++;
            float dd = 1.0f - g_sims[(size_t)(b*NMM + n)*NCLS + c];
            insK<5>(dd, n, lv, li);
        }
    }
    #pragma unroll
    for (int o = 16; o; o >>= 1) cnt += __shfl_xor_sync(0xffffffffu, cnt, o);
    __shared__ float sv[160];
    __shared__ int   si[160];
    #pragma unroll
    for (int j = 0; j < 5; j++) { sv[lane*5 + j] = lv[j]; si[lane*5 + j] = li[j]; }
    __syncwarp();
    if (lane == 0) {
        float fv[5]; int fi[5];
        #pragma unroll
        for (int j = 0; j < 5; j++) { fv[j] = -1e30f; fi[j] = 0x7fffffff; }
        for (int t = 0; t < 160; t++)
            if (si[t] != 0x7fffffff) insK<5>(sv[t], si[t], fv, fi);
        #pragma unroll
        for (int k = 0; k < 5; k++)
            g_topi[(size_t)bc*KB + k] = (k < cnt) ? fi[k] : -1;
    }
}

// (s2)
__global__ void pinv_kernel(const float* __restrict__ protos) {
    int c = blockIdx.x;
    int lane = threadIdx.x;
    const float4* r4 = (const float4*)(protos + (size_t)c * ND);
    float ss = 0.f;
    for (int t = lane; t < ND/4; t += 32) {
        float4 v = r4[t];
        ss += v.x*v.x + v.y*v.y + v.z*v.z + v.w*v.w;
    }
    #pragma unroll
    for (int o = 16; o; o >>= 1) ss += __shfl_xor_sync(0xffffffffu, ss, o);
    if (lane == 0) g_pinv[c] = 1.0f / fmaxf(sqrtf(ss), 1e-6f);
}

// (s2): column logsumexp of masked prototype-prototype similarities
__global__ void lseP_kernel(const float* __restrict__ protos) {
    int c = blockIdx.x;
    int tid = threadIdx.x;  // 128
    float val = -1e30f;
    if (tid < NCLS && tid != c) {
        const float4* a4 = (const float4*)(protos + (size_t)tid * ND);
        const float4* b4 = (const float4*)(protos + (size_t)c   * ND);
        float d = 0.f;
        for (int t = 0; t < ND/4; t++) {
            float4 a = __ldg(a4 + t), bb = __ldg(b4 + t);
            d += a.x*bb.x + a.y*bb.y + a.z*bb.z + a.w*bb.w;
        }
        val = d * g_pinv[tid] * g_pinv[c] / 0.1f;
    }
    __shared__ float sm[128];
    sm[tid] = val; __syncthreads();
    for (int o = 64; o; o >>= 1) { if (tid < o) sm[tid] = fmaxf(sm[tid], sm[tid+o]); __syncthreads(); }
    float mx = sm[0];
    __syncthreads();
    sm[tid] = (tid < NCLS && tid != c) ? expf(val - mx) : 0.f;
    __syncthreads();
    for (int o = 64; o; o >>= 1) { if (tid < o) sm[tid] += sm[tid+o]; __syncthreads(); }
    if (tid == 0) g_lseP[c] = mx + logf(sm[0]);
}

// (s2): column logsumexp of masked sample-prototype sims + combine
__global__ void lseS_kernel(const int* __restrict__ labels) {
    int c = blockIdx.x;
    int tid = threadIdx.x;  // 256
    float pin = g_pinv[c];
    float m = -1e30f, s = 0.f;
    for (int i = tid; i < NB*NMM; i += 256) {
        if (labels[i] == c) continue;
        float v = g_sims[(size_t)i*NCLS + c] * pin / 0.1f;
        if (v > m) { s = s * expf(m - v) + 1.f; m = v; }
        else       { s += expf(v - m); }
    }
    __shared__ float sm[256], ss[256];
    sm[tid] = m; ss[tid] = s;
    __syncthreads();
    for (int o = 128; o; o >>= 1) {
        if (tid < o) {
            float m2 = sm[tid+o], s2 = ss[tid+o];
            float M = fmaxf(sm[tid], m2);
            ss[tid] = ss[tid]*expf(sm[tid]-M) + s2*expf(m2-M);
            sm[tid] = M;
        }
        __syncthreads();
    }
    if (tid == 0) {
        float lse = sm[0] + logf(ss[0]);
        g_lseneg[c] = logaddexpf_(lse, g_lseP[c]);
    }
}

// (s2)
__global__ void cec_kernel(const int* __restrict__ labels) {
    int i = blockIdx.x * 256 + threadIdx.x;
    float term = 0.f;
    if (i < NB*NMM) {
        int l = labels[i];
        float pos = g_sims[(size_t)i*NCLS + l] * g_pinv[l] / 0.1f;
        term = -pos + logaddexpf_(pos, g_lseneg[l]);
    }
    __shared__ float sm[256];
    sm[threadIdx.x] = term;
    __syncthreads();
    for (int o = 128; o; o >>= 1) { if (threadIdx.x < o) sm[threadIdx.x] += sm[threadIdx.x+o]; __syncthreads(); }
    if (threadIdx.x == 0) atomicAdd(&g_acc[2], (double)sm[0]);
}

// (s0, after topk join): FUSED merge_gbar + focal: 8 boundary rows per block.
// Phase 1: per-warp g_bar into smem (no g_gbar global round trip).
// Phase 2: focal loss from smem.
__global__ __launch_bounds__(256) void merge_focal_kernel(const float* __restrict__ obj,
                                                          const float* __restrict__ Wc,
                                                          const float* __restrict__ bc) {
    __shared__ __align__(16) float4 gb4[8][ND/4];   // 8KB
    __shared__ int flags[8];
    __shared__ int bq[8][8];
    int w = threadIdx.x >> 5, lane = threadIdx.x & 31;
    int tid = threadIdx.x;
    int R = blockIdx.x*8 + w;
    int b = R / NROW;
    int ti = g_topi[R];
    bool valid = (ti >= 0);

    if (lane == 0) {
        int W = 0;
        if (valid) {
            size_t fb = ((size_t)(b*NMM + ti))*5;
            #pragma unroll
            for (int mm = 0; mm < 5; mm++) {
                float v = g_fv[fb + mm];
                bool nb = v > 0.0f;
                bq[w][mm] = nb ? g_fq[fb + mm] : -1;
                W += nb ? 1 : 0;
            }
        }
        bq[w][5] = W;
        flags[w] = (valid && W > 0) ? 1 : 0;
    }
    __syncwarp();
    int W = bq[w][5];
    if (valid && W > 0) {
        float invw = 1.0f / (1.0f + (float)W);
        int d0 = lane * 8;
        const float* mrow = g_matched + ((size_t)b*NMM + ti)*ND + d0;
        float acc[8];
        #pragma unroll
        for (int e = 0; e < 8; e++) acc[e] = mrow[e];
        #pragma unroll
        for (int mm = 0; mm < 5; mm++) {
            int q = bq[w][mm];
            if (q >= 0) {
                const float* ur = obj + ((size_t)b*NQ + q)*ND + d0;
                #pragma unroll
                for (int e = 0; e < 8; e++) acc[e] += ur[e];
            }
        }
        float* grow = (float*)gb4[w];
        #pragma unroll
        for (int e = 0; e < 8; e++) grow[d0 + e] = acc[e] * invw;
    }
    __syncthreads();

    int nv = flags[0]+flags[1]+flags[2]+flags[3]+flags[4]+flags[5]+flags[6]+flags[7];
    if (nv == 0) return;

    float fsum = 0.f;
    if (tid < NNC) {
        float xs[8];
        float bias = bc[tid];
        #pragma unroll
        for (int rr = 0; rr < 8; rr++) xs[rr] = bias;
        const float4* w4 = (const float4*)(Wc + (size_t)tid * ND);
        for (int t = 0; t < ND/4; t++) {
            float4 wv = __ldg(w4 + t);
            #pragma unroll
            for (int rr = 0; rr < 8; rr++) {
                float4 g = gb4[rr][t];
                xs[rr] += wv.x*g.x + wv.y*g.y + wv.z*g.z + wv.w*g.w;
            }
        }
        #pragma unroll
        for (int rr = 0; rr < 8; rr++) {
            if (!flags[rr]) continue;
            float x = xs[rr];
            float fl;
            if (tid == NNC - 1) {
                float sp = (x < 0.f) ? (-x + log1pf(expf(x))) : log1pf(expf(-x));
                float sn = 1.f / (1.f + expf(x));
                fl = 0.25f * sp * sn * sn;
            } else {
                float sp = (x > 0.f) ? (x + log1pf(expf(-x))) : log1pf(expf(x));
                float sg = 1.f / (1.f + expf(-x));
                fl = 0.75f * sp * sg * sg;
            }
            fsum += fl;
        }
    }
    __shared__ float red[256];
    red[tid] = fsum;
    __syncthreads();
    for (int o = 128; o; o >>= 1) { if (tid < o) red[tid] += red[tid+o]; __syncthreads(); }
    if (tid == 0) {
        atomicAdd(&g_acc[0], (double)(red[0] / 91.0f));
        atomicAdd(&g_acc[1], (double)nv);
    }
}

// (s0)
__global__ void finalize_kernel(float* out) {
    double ns = g_acc[1] < 1.0 ? 1.0 : g_acc[1];
    out[0] = (float)(g_acc[0] / ns);
    out[1] = (float)(g_acc[2] / (double)(NB*NMM));
}

// -------- launch (R9/R14 issue order) --------
extern "C" void kernel_launch(void* const* d_in, const int* in_sizes, int n_in,
                              void* d_out, int out_size) {
    const float* obj    = (const float*)d_in[0];
    const float* protos = (const float*)d_in[1];
    const float* Wc     = (const float*)d_in[2];
    const float* bc     = (const float*)d_in[3];
    const int*   src    = (const int*)d_in[4];
    const int*   labels = (const int*)d_in[5];
    float* out = (float*)d_out;

    static cudaStream_t s2 = 0;
    static cudaEvent_t ev0 = 0, ev_topk = 0, ev_cec = 0;
    if (!s2) {
        cudaStreamCreateWithFlags(&s2, cudaStreamNonBlocking);
        cudaEventCreateWithFlags(&ev0, cudaEventDisableTiming);
        cudaEventCreateWithFlags(&ev_topk, cudaEventDisableTiming);
        cudaEventCreateWithFlags(&ev_cec, cudaEventDisableTiming);
        cudaFuncSetAttribute(simbu_wmma_kernel,
                             cudaFuncAttributeMaxDynamicSharedMemorySize, SMEMT);
    }

    // stream 0: shared prologue
    pack_obj_kernel<<<(NB*NQ*32 + 255)/256, 256>>>(obj);            // 1
    gather_pack_kernel<<<(NB*MPAD*32 + 255)/256, 256>>>(obj, src);  // 2

    // fork: s2 runs the sims/topk/lse chain under the GEMM
    cudaEventRecord(ev0, 0);
    cudaStreamWaitEvent(s2, ev0, 0);

    sims_kernel<<<(NB*NMM)/16, 256, 0, s2>>>(protos);               // 3 (s2)
    {
        dim3 grid(NT, MPAD/128, NB);   // 15 x 3 x 32
        simbu_wmma_kernel<<<grid, 256, SMEMT>>>();                  // 4 (s0)
    }
    rerank_kernel<<<(NB*NMM*32 + 255)/256, 256>>>(obj);             // 5 (s0)
    topk_dists_kernel<<<NB*NCLS, 32, 0, s2>>>(labels);              // 6 (s2)
    cudaEventRecord(ev_topk, s2);                                   // merge only needs topk
    pinv_kernel<<<NCLS, 32, 0, s2>>>(protos);                       // 7 (s2)
    lseP_kernel<<<NCLS, 128, 0, s2>>>(protos);                      // 8 (s2)
    lseS_kernel<<<NCLS, 256, 0, s2>>>(labels);                      // 9 (s2)
    cec_kernel<<<(NB*NMM + 255)/256, 256, 0, s2>>>(labels);         // 10 (s2)
    cudaEventRecord(ev_cec, s2);                                    // finalize needs cec

    // early join: fused merge+focal overlaps with the lse/cec tail on s2
    cudaStreamWaitEvent(0, ev_topk, 0);
    merge_focal_kernel<<<(NB*NROW)/8, 256>>>(obj, Wc, bc);          // 11 (s0)

    cudaStreamWaitEvent(0, ev_cec, 0);
    finalize_kernel<<<1, 1>>>(out);                                 // 12 (s0)
}

// round 17
// speedup vs baseline: 1.0800x; 1.0800x over previous
#include <cuda_runtime.h>
#include <cuda_bf16.h>
#include <mma.h>
#include <cstdint>
#include <math.h>

using namespace nvcuda;

#define NB   32
#define NQ   900
#define NMM  300
#define MPAD 384            // matched rows padded for 128-tiles
#define ND   256
#define NCLS 90
#define NNC  91
#define KB   5
#define NCAND 5             // candidates per (row, nTile)
#define NT   15             // n tiles of 64 (15*64=960 >= 900)
#define NCTOT (NT*NCAND)    // 75 candidates per row
#define NRER 10             // exact-reranked candidates per row
#define NROW (NCLS*KB)      // 450 boundary rows per batch
#define NEGINF -1000000000.0f
#define SLD  72             // smem leading dim (bf16 elements), 144B rows
#define TILEA 18432u        // 128*72*2 bytes (A chunk)
#define TILEBB 9216u        // 64*72*2 bytes (B chunk)
#define BUFB  (TILEA + TILEBB)   // 27648 per buffer
#define SMEMT (2u*BUFB)          // 55296 total

// -------- scratch (device globals; no allocation allowed) --------
__device__ __align__(128) float g_matched[NB*NMM*ND];     // gathered matched embeddings (raw)
__device__ __align__(128) float g_minv[NB*NMM];           // 1/||matched||
__device__ __align__(128) float g_qinv[NB*NQ];            // 1/||obj||
__device__ __align__(128) int   g_ism[NB*NQ];             // is-matched mask per (b,q)
__device__ __align__(128) float g_sims[NB*NMM*NCLS];      // matched_n . protos (fp32 exact)
__device__ __align__(128) float g_pinv[NCLS];             // 1/||proto||
__device__ __align__(128) int   g_topi[NB*NROW];          // top-K_B indices per (b,c,k), -1 invalid
__device__ __align__(128) __nv_bfloat16 g_Mh[NB*MPAD*ND]; // matched_n bf16 (padded rows zero)
__device__ __align__(128) __nv_bfloat16 g_Bh[NB*NQ*ND];   // obj_n bf16
__device__ __align__(128) float g_pv[NB*NMM*NCTOT];       // approx top5 values per (row,nTile)
__device__ __align__(128) int   g_pq[NB*NMM*NCTOT];       // approx top5 q per (row,nTile)
__device__ __align__(128) float g_fv[NB*NMM*KB];          // exact top5 values per matched row
__device__ __align__(128) int   g_fq[NB*NMM*KB];          // exact top5 q per matched row
__device__ __align__(128) float g_gbar[NB*NROW*ND];       // subgroup means
__device__ __align__(128) int   g_sgv[NB*NROW];           // sg_valid
__device__ __align__(128) float g_lseP[NCLS];
__device__ __align__(128) float g_lseneg[NCLS];
__device__ double g_acc[3];   // 0: sum fl, 1: count sg_valid, 2: sum cec terms

// -------- helpers --------
__device__ __forceinline__ float logaddexpf_(float a, float b) {
    float m = fmaxf(a, b);
    return m + log1pf(expf(-fabsf(a - b)));
}

// insert (v,id) into sorted-desc top-K, tie -> lower id first (jax top_k semantics)
template<int K>
__device__ __forceinline__ void insK(float v, int id, float* vals, int* ids) {
    #pragma unroll
    for (int j = 0; j < K; j++) {
        bool better = (v > vals[j]) || (v == vals[j] && id < ids[j]);
        if (better) {
            float tv = vals[j]; int ti = ids[j];
            vals[j] = v; ids[j] = id;
            v = tv; id = ti;
        }
    }
}

__device__ __forceinline__ void cp16(uint32_t s, const void* g) {
    asm volatile("cp.async.ca.shared.global [%0], [%1], 16;" :: "r"(s), "l"(g));
}
__device__ __forceinline__ void cp16z(uint32_t s, const void* g, int sz) {
    asm volatile("cp.async.ca.shared.global [%0], [%1], 16, %2;" :: "r"(s), "l"(g), "r"(sz));
}

// ordered-uint encoding of float: preserves > ordering
__device__ __forceinline__ unsigned int ford(float f) {
    unsigned int u = __float_as_uint(f);
    return (u & 0x80000000u) ? ~u : (u | 0x80000000u);
}

__device__ __forceinline__ uint2 pack_bf16x4(float4 a) {
    __nv_bfloat162 lo = __floats2bfloat162_rn(a.x, a.y);
    __nv_bfloat162 hi = __floats2bfloat162_rn(a.z, a.w);
    uint2 r;
    r.x = *(unsigned*)&lo;
    r.y = *(unsigned*)&hi;
    return r;
}

// -------- kernels --------

// one warp per obj row: normalize + bf16 pack + qinv + clear is_m (+ zero g_acc)
__global__ void pack_obj_kernel(const float* __restrict__ obj) {
    if (blockIdx.x == 0 && threadIdx.x < 3) g_acc[threadIdx.x] = 0.0;
    int warp = (blockIdx.x * blockDim.x + threadIdx.x) >> 5;
    int lane = threadIdx.x & 31;
    if (warp >= NB*NQ) return;
    const float4* r4 = (const float4*)(obj + (size_t)warp * ND);
    float4 a = r4[lane];
    float4 c = r4[lane + 32];
    float ss = a.x*a.x + a.y*a.y + a.z*a.z + a.w*a.w
             + c.x*c.x + c.y*c.y + c.z*c.z + c.w*c.w;
    #pragma unroll
    for (int o = 16; o; o >>= 1) ss += __shfl_xor_sync(0xffffffffu, ss, o);
    float inv = 1.0f / fmaxf(sqrtf(ss), 1e-12f);
    float4 an = make_float4(a.x*inv, a.y*inv, a.z*inv, a.w*inv);
    float4 cn = make_float4(c.x*inv, c.y*inv, c.z*inv, c.w*inv);
    ((uint2*)g_Bh)[(size_t)warp*64 + lane]      = pack_bf16x4(an);
    ((uint2*)g_Bh)[(size_t)warp*64 + lane + 32] = pack_bf16x4(cn);
    if (lane == 0) { g_ism[warp] = 0; g_qinv[warp] = inv; }
}

// one warp per padded matched row: gather + norm + is_m + fp32 copy + bf16 pack
__global__ void gather_pack_kernel(const float* __restrict__ obj, const int* __restrict__ src) {
    int warp = (blockIdx.x * blockDim.x + threadIdx.x) >> 5;
    int lane = threadIdx.x & 31;
    if (warp >= NB*MPAD) return;
    int b = warp / MPAD, n = warp - b*MPAD;
    size_t mrow = (size_t)b*MPAD + n;
    if (n >= NMM) {
        uint2 z = make_uint2(0,0);
        ((uint2*)g_Mh)[mrow*64 + lane] = z;
        ((uint2*)g_Mh)[mrow*64 + lane + 32] = z;
        return;
    }
    int idx = src[b*NMM + n];
    const float4* r4 = (const float4*)(obj + ((size_t)b*NQ + idx) * ND);
    float4 a = r4[lane];
    float4 c = r4[lane + 32];
    float4* o4 = (float4*)(g_matched + ((size_t)b*NMM + n) * ND);
    o4[lane] = a; o4[lane + 32] = c;
    float ss = a.x*a.x + a.y*a.y + a.z*a.z + a.w*a.w
             + c.x*c.x + c.y*c.y + c.z*c.z + c.w*c.w;
    #pragma unroll
    for (int o = 16; o; o >>= 1) ss += __shfl_xor_sync(0xffffffffu, ss, o);
    float inv = 1.0f / fmaxf(sqrtf(ss), 1e-12f);
    float4 an = make_float4(a.x*inv, a.y*inv, a.z*inv, a.w*inv);
    float4 cn = make_float4(c.x*inv, c.y*inv, c.z*inv, c.w*inv);
    ((uint2*)g_Mh)[mrow*64 + lane]      = pack_bf16x4(an);
    ((uint2*)g_Mh)[mrow*64 + lane + 32] = pack_bf16x4(cn);
    if (lane == 0) {
        g_minv[b*NMM + n] = inv;
        g_ism[b*NQ + idx] = 1;
    }
}

// (s2): sims[r, c] = minv[r] * (matched[r] . protos[c]) ; fp32 exact
__global__ __launch_bounds__(256) void sims_kernel(const float* __restrict__ protos) {
    __shared__ __align__(16) float As[16*ND];
    __shared__ float sminv[16];
    int r0 = blockIdx.x * 16;
    int tid = threadIdx.x;
    float4* s4 = (float4*)As;
    const float4* gm4 = (const float4*)(g_matched + (size_t)r0 * ND);
    for (int i = tid; i < 16*ND/4; i += 256) s4[i] = gm4[i];
    if (tid < 16) sminv[tid] = g_minv[r0 + tid];
    __syncthreads();
    for (int o = tid; o < 16*NCLS; o += 256) {
        int r = o / NCLS;
        int c = o - r*NCLS;
        const float4* p4 = (const float4*)(protos + (size_t)c * ND);
        const float4* a4 = (const float4*)(As + r * ND);
        float acc = 0.f;
        #pragma unroll 8
        for (int t = 0; t < ND/4; t++) {
            float4 a = a4[t];
            float4 p = __ldg(p4 + t);
            acc += a.x*p.x + a.y*p.y + a.z*p.z + a.w*p.w;
        }
        g_sims[(size_t)(r0 + r)*NCLS + c] = acc * sminv[r];
    }
}

// (s0): S = matched_n @ obj_n^T via WMMA bf16 (single term — exact rerank downstream
// absorbs the ~2.6e-4 dot noise; candidate-set membership is all that matters).
// Block tile 128x64: 4 acc fragments/warp -> 4 CTAs/SM.
__global__ __launch_bounds__(256, 4) void simbu_wmma_kernel() {
    extern __shared__ __align__(16) char dsm[];   // [A0(18KB), B0(9KB), A1, B1]
    __shared__ int smask[64];
    int tid = threadIdx.x, wid = tid >> 5, lane = tid & 31;
    int nT = blockIdx.x, mT = blockIdx.y, b = blockIdx.z;
    const int mBase = mT*128, nBase = nT*64;
    uint32_t sbase = (uint32_t)__cvta_generic_to_shared(dsm);

    if (tid < 64) {
        int n = nBase + tid;
        smask[tid] = (n < NQ) ? g_ism[b*NQ + n] : 2;
    }

    wmma::fragment<wmma::accumulator, 16, 16, 16, float> acc[4];
    #pragma unroll
    for (int i = 0; i < 4; i++) wmma::fill_fragment(acc[i], 0.0f);

    // 4 K-chunks of 64 bf16 (K=256), single segment (Mh x Bh)
    #define ISSUE_CHUNK(chunk) do {                                                   \
        int kc_ = (chunk), bi_ = (chunk) & 1;                                         \
        uint32_t sa_ = sbase + (uint32_t)bi_ * BUFB;                                  \
        uint32_t sb_ = sa_ + TILEA;                                                   \
        _Pragma("unroll")                                                             \
        for (int i_ = 0; i_ < 4; i_++) {                                              \
            int e_ = i_*256 + tid;                                                    \
            int r_ = e_ >> 3, g_ = e_ & 7;                                            \
            cp16(sa_ + (uint32_t)(r_*144 + g_*16),                                    \
                 g_Mh + ((size_t)(b*MPAD + mBase + r_)*ND + kc_*64 + g_*8));          \
        }                                                                             \
        _Pragma("unroll")                                                             \
        for (int i_ = 0; i_ < 2; i_++) {                                              \
            int e_ = i_*256 + tid;                                                    \
            int r_ = e_ >> 3, g_ = e_ & 7;                                            \
            int br_ = nBase + r_;                                                     \
            cp16z(sb_ + (uint32_t)(r_*144 + g_*16),                                   \
                  g_Bh + ((size_t)b*NQ + (br_ < NQ ? br_ : 0))*ND + kc_*64 + g_*8,    \
                  (br_ < NQ) ? 16 : 0);                                               \
        }                                                                             \
        asm volatile("cp.async.commit_group;" ::: "memory");                          \
    } while (0)

    ISSUE_CHUNK(0);
    for (int c = 0; c < 4; c++) {
        if (c + 1 < 4) {
            ISSUE_CHUNK(c + 1);
            asm volatile("cp.async.wait_group 1;" ::: "memory");
        } else {
            asm volatile("cp.async.wait_group 0;" ::: "memory");
        }
        __syncthreads();
        int bi = c & 1;
        const __nv_bfloat16* Ab = (const __nv_bfloat16*)(dsm + (size_t)bi*BUFB);
        const __nv_bfloat16* Bb = (const __nv_bfloat16*)(dsm + (size_t)bi*BUFB + TILEA);
        #pragma unroll
        for (int ks = 0; ks < 4; ks++) {
            wmma::fragment<wmma::matrix_a, 16, 16, 16, __nv_bfloat16, wmma::row_major> af;
            wmma::load_matrix_sync(af, Ab + (wid*16)*SLD + ks*16, SLD);
            #pragma unroll
            for (int nt = 0; nt < 4; nt++) {
                wmma::fragment<wmma::matrix_b, 16, 16, 16, __nv_bfloat16, wmma::col_major> bf;
                wmma::load_matrix_sync(bf, Bb + (nt*16)*SLD + ks*16, SLD);
                wmma::mma_sync(acc[nt], af, bf, acc[nt]);
            }
        }
        __syncthreads();
    }
    #undef ISSUE_CHUNK

    // epilogue: per-warp 16x20 f32 staging buffer aliased over buffer 0
    float* ebuf = reinterpret_cast<float*>(dsm) + (size_t)wid * 320;
    float tv[NCAND]; int tq[NCAND];
    #pragma unroll
    for (int j = 0; j < NCAND; j++) { tv[j] = -1e30f; tq[j] = 0x7fffffff; }
    #pragma unroll
    for (int nt = 0; nt < 4; nt++) {
        wmma::store_matrix_sync(ebuf, acc[nt], 20, wmma::mem_row_major);
        __syncwarp();
        if (lane < 16) {
            #pragma unroll
            for (int cc = 0; cc < 16; cc++) {
                int col = nt*16 + cc;
                int mk = smask[col];
                float v; int id;
                if (mk == 2)      { v = -1e30f; id = 0x7fffffff; }
                else if (mk == 1) { v = NEGINF; id = nBase + col; }
                else              { v = ebuf[lane*20 + cc]; id = nBase + col; }
                if (!(v < tv[NCAND-1])) insK<NCAND>(v, id, tv, tq);
            }
        }
        __syncwarp();
    }
    if (lane < 16) {
        int m = mBase + wid*16 + lane;
        if (m < NMM) {
            size_t base = ((size_t)(b*NMM + m)*NT + nT)*NCAND;
            #pragma unroll
            for (int j = 0; j < NCAND; j++) { g_pv[base+j] = tv[j]; g_pq[base+j] = tq[j]; }
        }
    }
}

// (s0): warp-parallel approx preselect (top-10 of 75 via iterated warp-argmax on
// packed keys), then exact fp32 rerank of the 10.
__global__ __launch_bounds__(256) void rerank_kernel(const float* __restrict__ obj) {
    int warp = (blockIdx.x * blockDim.x + threadIdx.x) >> 5;
    int lane = threadIdx.x & 31;
    if (warp >= NB*NMM) return;
    int b = warp / NMM;
    float minv = g_minv[warp];
    const float4* mr = (const float4*)(g_matched + (size_t)warp * ND);
    float4 m0 = mr[lane*2], m1 = mr[lane*2 + 1];

    // lane owns candidates lane, lane+32, lane+64 (valid < 75); pack sortable keys.
    size_t pbase = (size_t)warp * NCTOT;
    unsigned long long k0 = 0ull, k1 = 0ull, k2 = 0ull;
    {
        float v = g_pv[pbase + lane];
        int   q = g_pq[pbase + lane];
        if (v > -1e8f && q != 0x7fffffff)
            k0 = ((unsigned long long)ford(v) << 32) | (unsigned)(0x7fffffff - q);
        float v1 = g_pv[pbase + lane + 32];
        int   q1 = g_pq[pbase + lane + 32];
        if (v1 > -1e8f && q1 != 0x7fffffff)
            k1 = ((unsigned long long)ford(v1) << 32) | (unsigned)(0x7fffffff - q1);
        if (lane + 64 < NCTOT) {
            float v2 = g_pv[pbase + lane + 64];
            int   q2 = g_pq[pbase + lane + 64];
            if (v2 > -1e8f && q2 != 0x7fffffff)
                k2 = ((unsigned long long)ford(v2) << 32) | (unsigned)(0x7fffffff - q2);
        }
    }

    // iterated warp-argmax: select top-NRER keys
    int selq[NRER];
    #pragma unroll
    for (int t = 0; t < NRER; t++) {
        unsigned long long m = (k0 > k1) ? k0 : k1;
        if (k2 > m) m = k2;
        #pragma unroll
        for (int o = 16; o; o >>= 1) {
            unsigned long long m2 = __shfl_xor_sync(0xffffffffu, m, o);
            if (m2 > m) m = m2;
        }
        selq[t] = (m != 0ull) ? (0x7fffffff - (int)(m & 0xffffffffu)) : -1;
        if (k0 == m) k0 = 0ull;
        if (k1 == m) k1 = 0ull;
        if (k2 == m) k2 = 0ull;
    }

    // exact rerank: buffered partial dots for MLP, then reduce
    float pd[NRER];
    #pragma unroll
    for (int t = 0; t < NRER; t++) {
        float d = 0.f;
        int q = selq[t];
        if (q >= 0) {
            const float4* ur = (const float4*)(obj + ((size_t)b*NQ + q) * ND);
            float4 u0 = ur[lane*2], u1 = ur[lane*2 + 1];
            d = m0.x*u0.x + m0.y*u0.y + m0.z*u0.z + m0.w*u0.w
              + m1.x*u1.x + m1.y*u1.y + m1.z*u1.z + m1.w*u1.w;
        }
        pd[t] = d;
    }
    float fv[5]; int fq[5];
    #pragma unroll
    for (int j = 0; j < 5; j++) { fv[j] = -1e30f; fq[j] = 0x7fffffff; }
    #pragma unroll
    for (int t = 0; t < NRER; t++) {
        float d = pd[t];
        #pragma unroll
        for (int o = 16; o; o >>= 1) d += __shfl_xor_sync(0xffffffffu, d, o);
        int q = selq[t];
        if (q >= 0) {
            float sim = d * minv * g_qinv[b*NQ + q];
            insK<5>(sim, q, fv, fq);
        }
    }
    if (lane == 0) {
        #pragma unroll
        for (int j = 0; j < 5; j++) {
            g_fv[(size_t)warp*5 + j] = fv[j];
            g_fq[(size_t)warp*5 + j] = fq[j];
        }
    }
}

// (s2): per (b,c): top-5 of dist = 1 - sim over n with label==c
__global__ void topk_dists_kernel(const int* __restrict__ labels) {
    int bc = blockIdx.x;
    int b = bc / NCLS, c = bc - b*NCLS;
    int lane = threadIdx.x;
    float lv[5]; int li[5];
    #pragma unroll
    for (int j = 0; j < 5; j++) { lv[j] = -1e30f; li[j] = 0x7fffffff; }
    int cnt = 0;
    for (int n = lane; n < NMM; n += 32) {
        if (labels[b*NMM + n] == c) {
            cnt++;
            float dd = 1.0f - g_sims[(size_t)(b*NMM + n)*NCLS + c];
            insK<5>(dd, n, lv, li);
        }
    }
    #pragma unroll
    for (int o = 16; o; o >>= 1) cnt += __shfl_xor_sync(0xffffffffu, cnt, o);
    __shared__ float sv[160];
    __shared__ int   si[160];
    #pragma unroll
    for (int j = 0; j < 5; j++) { sv[lane*5 + j] = lv[j]; si[lane*5 + j] = li[j]; }
    __syncwarp();
    if (lane == 0) {
        float fv[5]; int fi[5];
        #pragma unroll
        for (int j = 0; j < 5; j++) { fv[j] = -1e30f; fi[j] = 0x7fffffff; }
        for (int t = 0; t < 160; t++)
            if (si[t] != 0x7fffffff) insK<5>(sv[t], si[t], fv, fi);
        #pragma unroll
        for (int k = 0; k < 5; k++)
            g_topi[(size_t)bc*KB + k] = (k < cnt) ? fi[k] : -1;
    }
}

// (s2)
__global__ void pinv_kernel(const float* __restrict__ protos) {
    int c = blockIdx.x;
    int lane = threadIdx.x;
    const float4* r4 = (const float4*)(protos + (size_t)c * ND);
    float ss = 0.f;
    for (int t = lane; t < ND/4; t += 32) {
        float4 v = r4[t];
        ss += v.x*v.x + v.y*v.y + v.z*v.z + v.w*v.w;
    }
    #pragma unroll
    for (int o = 16; o; o >>= 1) ss += __shfl_xor_sync(0xffffffffu, ss, o);
    if (lane == 0) g_pinv[c] = 1.0f / fmaxf(sqrtf(ss), 1e-6f);
}

// (s2): column logsumexp of masked prototype-prototype similarities
__global__ void lseP_kernel(const float* __restrict__ protos) {
    int c = blockIdx.x;
    int tid = threadIdx.x;  // 128
    float val = -1e30f;
    if (tid < NCLS && tid != c) {
        const float4* a4 = (const float4*)(protos + (size_t)tid * ND);
        const float4* b4 = (const float4*)(protos + (size_t)c   * ND);
        float d = 0.f;
        for (int t = 0; t < ND/4; t++) {
            float4 a = __ldg(a4 + t), bb = __ldg(b4 + t);
            d += a.x*bb.x + a.y*bb.y + a.z*bb.z + a.w*bb.w;
        }
        val = d * g_pinv[tid] * g_pinv[c] / 0.1f;
    }
    __shared__ float sm[128];
    sm[tid] = val; __syncthreads();
    for (int o = 64; o; o >>= 1) { if (tid < o) sm[tid] = fmaxf(sm[tid], sm[tid+o]); __syncthreads(); }
    float mx = sm[0];
    __syncthreads();
    sm[tid] = (tid < NCLS && tid != c) ? expf(val - mx) : 0.f;
    __syncthreads();
    for (int o = 64; o; o >>= 1) { if (tid < o) sm[tid] += sm[tid+o]; __syncthreads(); }
    if (tid == 0) g_lseP[c] = mx + logf(sm[0]);
}

// (s2): column logsumexp of masked sample-prototype sims + combine
__global__ void lseS_kernel(const int* __restrict__ labels) {
    int c = blockIdx.x;
    int tid = threadIdx.x;  // 256
    float pin = g_pinv[c];
    float m = -1e30f, s = 0.f;
    for (int i = tid; i < NB*NMM; i += 256) {
        if (labels[i] == c) continue;
        float v = g_sims[(size_t)i*NCLS + c] * pin / 0.1f;
        if (v > m) { s = s * expf(m - v) + 1.f; m = v; }
        else       { s += expf(v - m); }
    }
    __shared__ float sm[256], ss[256];
    sm[tid] = m; ss[tid] = s;
    __syncthreads();
    for (int o = 128; o; o >>= 1) {
        if (tid < o) {
            float m2 = sm[tid+o], s2 = ss[tid+o];
            float M = fmaxf(sm[tid], m2);
            ss[tid] = ss[tid]*expf(sm[tid]-M) + s2*expf(m2-M);
            sm[tid] = M;
        }
        __syncthreads();
    }
    if (tid == 0) {
        float lse = sm[0] + logf(ss[0]);
        g_lseneg[c] = logaddexpf_(lse, g_lseP[c]);
    }
}

// (s2)
__global__ void cec_kernel(const int* __restrict__ labels) {
    int i = blockIdx.x * 256 + threadIdx.x;
    float term = 0.f;
    if (i < NB*NMM) {
        int l = labels[i];
        float pos = g_sims[(size_t)i*NCLS + l] * g_pinv[l] / 0.1f;
        term = -pos + logaddexpf_(pos, g_lseneg[l]);
    }
    __shared__ float sm[256];
    sm[threadIdx.x] = term;
    __syncthreads();
    for (int o = 128; o; o >>= 1) { if (threadIdx.x < o) sm[threadIdx.x] += sm[threadIdx.x+o]; __syncthreads(); }
    if (threadIdx.x == 0) atomicAdd(&g_acc[2], (double)sm[0]);
}

// (s0, after topk join): per boundary row: read exact top-5 -> g_bar + sg_valid
__global__ __launch_bounds__(256) void merge_gbar_kernel(const float* __restrict__ obj) {
    __shared__ int bq[8][8];
    int w = threadIdx.x >> 5, lane = threadIdx.x & 31;
    int R = blockIdx.x*8 + w;
    int b = R / NROW;
    int ti = g_topi[R];
    if (ti < 0) { if (lane == 0) g_sgv[R] = 0; return; }
    size_t fb = ((size_t)(b*NMM + ti))*5;
    if (lane == 0) {
        int W = 0;
        #pragma unroll
        for (int mm = 0; mm < 5; mm++) {
            float v = g_fv[fb + mm];
            bool nb = v > 0.0f;
            bq[w][mm] = nb ? g_fq[fb + mm] : -1;
            W += nb ? 1 : 0;
        }
        bq[w][5] = W;
    }
    __syncwarp();
    int W = bq[w][5];
    if (W == 0) { if (lane == 0) g_sgv[R] = 0; return; }
    if (lane == 0) g_sgv[R] = 1;
    float invw = 1.0f / (1.0f + (float)W);
    int d0 = lane * 8;
    const float* mrow = g_matched + ((size_t)b*NMM + ti)*ND + d0;
    float acc[8];
    #pragma unroll
    for (int e = 0; e < 8; e++) acc[e] = mrow[e];
    #pragma unroll
    for (int mm = 0; mm < 5; mm++) {
        int q = bq[w][mm];
        if (q >= 0) {
            const float* ur = obj + ((size_t)b*NQ + q)*ND + d0;
            #pragma unroll
            for (int e = 0; e < 8; e++) acc[e] += ur[e];
        }
    }
    float* gr = g_gbar + (size_t)R*ND + d0;
    #pragma unroll
    for (int e = 0; e < 8; e++) gr[e] = acc[e] * invw;
}

// (s0): focal loss over valid subgroups; 8 rows per block
__global__ __launch_bounds__(128) void focal_kernel(const float* __restrict__ Wc,
                                                    const float* __restrict__ bc) {
    int r0 = blockIdx.x * 8;
    int tid = threadIdx.x;
    __shared__ __align__(16) float4 gb4[8][ND/4];
    __shared__ int flags[8];
    if (tid < 8) flags[tid] = g_sgv[r0 + tid];
    for (int t = tid; t < 8*(ND/4); t += 128) {
        int rr = t >> 6, tt = t & 63;
        gb4[rr][tt] = ((const float4*)(g_gbar + (size_t)(r0+rr)*ND))[tt];
    }
    __syncthreads();
    int nv = flags[0]+flags[1]+flags[2]+flags[3]+flags[4]+flags[5]+flags[6]+flags[7];
    if (nv == 0) return;

    float fsum = 0.f;
    if (tid < NNC) {
        float xs[8];
        float bias = bc[tid];
        #pragma unroll
        for (int rr = 0; rr < 8; rr++) xs[rr] = bias;
        const float4* w4 = (const float4*)(Wc + (size_t)tid * ND);
        for (int t = 0; t < ND/4; t++) {
            float4 w = __ldg(w4 + t);
            #pragma unroll
            for (int rr = 0; rr < 8; rr++) {
                float4 g = gb4[rr][t];
                xs[rr] += w.x*g.x + w.y*g.y + w.z*g.z + w.w*g.w;
            }
        }
        #pragma unroll
        for (int rr = 0; rr < 8; rr++) {
            if (!flags[rr]) continue;
            float x = xs[rr];
            float fl;
            if (tid == NNC - 1) {
                float sp = (x < 0.f) ? (-x + log1pf(expf(x))) : log1pf(expf(-x));
                float sn = 1.f / (1.f + expf(x));
                fl = 0.25f * sp * sn * sn;
            } else {
                float sp = (x > 0.f) ? (x + log1pf(expf(-x))) : log1pf(expf(x));
                float sg = 1.f / (1.f + expf(-x));
                fl = 0.75f * sp * sg * sg;
            }
            fsum += fl;
        }
    }
    __shared__ float red[128];
    red[tid] = fsum;
    __syncthreads();
    for (int o = 64; o; o >>= 1) { if (tid < o) red[tid] += red[tid+o]; __syncthreads(); }
    if (tid == 0) {
        atomicAdd(&g_acc[0], (double)(red[0] / 91.0f));
        atomicAdd(&g_acc[1], (double)nv);
    }
}

// (s0)
__global__ void finalize_kernel(float* out) {
    double ns = g_acc[1] < 1.0 ? 1.0 : g_acc[1];
    out[0] = (float)(g_acc[0] / ns);
    out[1] = (float)(g_acc[2] / (double)(NB*NMM));
}

// -------- launch (R9/R14/R15 issue order) --------
extern "C" void kernel_launch(void* const* d_in, const int* in_sizes, int n_in,
                              void* d_out, int out_size) {
    const float* obj    = (const float*)d_in[0];
    const float* protos = (const float*)d_in[1];
    const float* Wc     = (const float*)d_in[2];
    const float* bc     = (const float*)d_in[3];
    const int*   src    = (const int*)d_in[4];
    const int*   labels = (const int*)d_in[5];
    float* out = (float*)d_out;

    static cudaStream_t s2 = 0;
    static cudaEvent_t ev0 = 0, ev_topk = 0, ev_cec = 0;
    if (!s2) {
        cudaStreamCreateWithFlags(&s2, cudaStreamNonBlocking);
        cudaEventCreateWithFlags(&ev0, cudaEventDisableTiming);
        cudaEventCreateWithFlags(&ev_topk, cudaEventDisableTiming);
        cudaEventCreateWithFlags(&ev_cec, cudaEventDisableTiming);
        cudaFuncSetAttribute(simbu_wmma_kernel,
                             cudaFuncAttributeMaxDynamicSharedMemorySize, SMEMT);
    }

    // stream 0: shared prologue
    pack_obj_kernel<<<(NB*NQ*32 + 255)/256, 256>>>(obj);            // 1
    gather_pack_kernel<<<(NB*MPAD*32 + 255)/256, 256>>>(obj, src);  // 2

    // fork: s2 runs the sims/topk/lse chain under the GEMM
    cudaEventRecord(ev0, 0);
    cudaStreamWaitEvent(s2, ev0, 0);

    sims_kernel<<<(NB*NMM)/16, 256, 0, s2>>>(protos);               // 3 (s2)
    {
        dim3 grid(NT, MPAD/128, NB);   // 15 x 3 x 32
        simbu_wmma_kernel<<<grid, 256, SMEMT>>>();                  // 4 (s0)
    }
    rerank_kernel<<<(NB*NMM*32 + 255)/256, 256>>>(obj);             // 5 (s0)
    topk_dists_kernel<<<NB*NCLS, 32, 0, s2>>>(labels);              // 6 (s2)
    cudaEventRecord(ev_topk, s2);                                   // merge only needs topk
    pinv_kernel<<<NCLS, 32, 0, s2>>>(protos);                       // 7 (s2)
    lseP_kernel<<<NCLS, 128, 0, s2>>>(protos);                      // 8 (s2)
    lseS_kernel<<<NCLS, 256, 0, s2>>>(labels);                      // 9 (s2)
    cec_kernel<<<(NB*NMM + 255)/256, 256, 0, s2>>>(labels);         // 10 (s2)
    cudaEventRecord(ev_cec, s2);                                    // finalize needs cec

    // early join: merge/focal overlap with the lse/cec tail on s2
    cudaStreamWaitEvent(0, ev_topk, 0);
    merge_gbar_kernel<<<(NB*NROW)/8, 256>>>(obj);                   // 11 (s0)
    focal_kernel<<<(NB*NROW)/8, 128>>>(Wc, bc);                     // 12 (s0)

    cudaStreamWaitEvent(0, ev_cec, 0);
    finalize_kernel<<<1, 1>>>(out);                                 // 13 (s0)
}